// round 14
// baseline (speedup 1.0000x reference)
#include <cuda_runtime.h>
#include <cuda_fp16.h>
#include <math.h>
#include <stdint.h>

#define S_LEN 512
#define BATCH 128
#define INPUT 512
#define HID   1024
#define G4    4096            // 4*HID, permuted rows: n' = j*4 + gate
#define MX    (S_LEN*BATCH)   // 65536
#define NBLK  128

// K-strips of 32 fp16, padded pitch 40 (80B rows, conflict-free ldmatrix).
// A-strip = 128 rows x 40 = 5120 elems (10240B). B-strip = 32 x 40 (2560B).
#define ASTRIP 5120
#define BSTRIP 1280

// ---------------- device scratch (static, no runtime allocation) ----------
// x image: [mt 512][s 16][128][40] fp16
__device__ __half g_xaug2[(size_t)512 * 16 * ASTRIP];     // ~84MB
// W_ih image: [nt 32][s 16][128][40] fp16
__device__ __half g_wih2[(size_t)32 * 16 * ASTRIP];       // ~5.2MB
// W_hh image: [nb 128][s 32][32][40] fp16
__device__ __half g_whh2[(size_t)128 * 32 * BSTRIP];      // ~10.5MB
__device__ float  g_bias[G4];
// x_proj blocked for step prefetch: [t 512][nb 128][b 128][32] fp32 (1GiB)
__device__ float  g_xproj[(size_t)S_LEN * NBLK * BATCH * 32];
__device__ float  g_c[BATCH * HID];
__device__ float  g_h[BATCH * HID];
// recurrent h: [pp 2][s 32][128 b][40] fp16, ping-pong
__device__ __half g_haug2[2][32 * ASTRIP];
// grid barrier: monotonic counter, reset by init_state_kernel each launch
__device__ unsigned g_cnt;

// ---------------- helpers ----------------
__device__ __forceinline__ uint32_t cvta_s(const void* p) {
    return (uint32_t)__cvta_generic_to_shared(p);
}
__device__ __forceinline__ void ldsm4(uint32_t r[4], uint32_t a) {
    asm volatile("ldmatrix.sync.aligned.m8n8.x4.shared.b16 {%0,%1,%2,%3}, [%4];\n"
                 : "=r"(r[0]), "=r"(r[1]), "=r"(r[2]), "=r"(r[3]) : "r"(a));
}
__device__ __forceinline__ void mma_f16(float* c, const uint32_t* a,
                                        uint32_t b0, uint32_t b1) {
    asm volatile(
        "mma.sync.aligned.m16n8k16.row.col.f32.f16.f16.f32 "
        "{%0,%1,%2,%3},{%4,%5,%6,%7},{%8,%9},{%0,%1,%2,%3};\n"
        : "+f"(c[0]), "+f"(c[1]), "+f"(c[2]), "+f"(c[3])
        : "r"(a[0]), "r"(a[1]), "r"(a[2]), "r"(a[3]), "r"(b0), "r"(b1));
}
__device__ __forceinline__ void mbar_init(void* m, uint32_t cnt) {
    asm volatile("mbarrier.init.shared.b64 [%0], %1;\n"
                 :: "r"(cvta_s(m)), "r"(cnt) : "memory");
}
__device__ __forceinline__ void mbar_expect(uint32_t mb, uint32_t bytes) {
    asm volatile("mbarrier.arrive.expect_tx.shared.b64 _, [%0], %1;\n"
                 :: "r"(mb), "r"(bytes) : "memory");
}
__device__ __forceinline__ void bulk_g2s(void* dst, const void* src,
                                         uint32_t bytes, uint32_t mb) {
    asm volatile("cp.async.bulk.shared::cta.global.mbarrier::complete_tx::bytes "
                 "[%0], [%1], %2, [%3];\n"
                 :: "r"(cvta_s(dst)), "l"(src), "r"(bytes), "r"(mb) : "memory");
}
__device__ __forceinline__ void mbar_wait(void* m, uint32_t parity) {
    uint32_t a = cvta_s(m);
    asm volatile(
        "{\n.reg .pred P;\n"
        "W_%=:\n"
        "mbarrier.try_wait.parity.shared.b64 P, [%0], %1;\n"
        "@!P bra W_%=;\n}\n"
        :: "r"(a), "r"(parity) : "memory");
}
// HW tanh (1 MUFU op, sm_75+). sigmoid via tanh: 1 MUFU + FMA, no RCP.
__device__ __forceinline__ float tanh_hw(float x) {
    float y;
    asm("tanh.approx.f32 %0, %1;" : "=f"(y) : "f"(x));
    return y;
}
__device__ __forceinline__ float fsigmoid(float x) {
    return fmaf(tanh_hw(0.5f * x), 0.5f, 0.5f);
}
__device__ __forceinline__ float ftanh(float x) { return tanh_hw(x); }
__device__ __forceinline__ uint32_t pack2(float a, float b) {
    __half2 h = __floats2half2_rn(a, b);
    return *(uint32_t*)&h;
}

// ---------------- prep kernels (vectorized) ----------------
__global__ void prep_x_kernel(const float* __restrict__ X) {
    size_t i4 = (size_t)blockIdx.x * 256 + threadIdx.x;
    if (i4 >= (size_t)MX * INPUT / 4) return;
    int m = (int)(i4 >> 7), kq = (int)(i4 & 127) * 4;
    int mt = m >> 7, mr = m & 127;
    int s = kq >> 5, kc = kq & 31;
    float4 v = *(const float4*)(X + (size_t)m * INPUT + kq);
    uint2 o; o.x = pack2(v.x, v.y); o.y = pack2(v.z, v.w);
    *(uint2*)(g_xaug2 + (size_t)(mt * 16 + s) * ASTRIP + mr * 40 + kc) = o;
}
__global__ void prep_wih_kernel(const float* __restrict__ W) {
    int i4 = blockIdx.x * 256 + threadIdx.x;
    if (i4 >= G4 * INPUT / 4) return;
    int r = i4 >> 7, kq = (i4 & 127) * 4;
    int g = r >> 10, j = r & 1023;
    int np = j * 4 + g;
    int nt = np >> 7, nr = np & 127;
    int s = kq >> 5, kc = kq & 31;
    float4 v = *(const float4*)(W + (size_t)r * INPUT + kq);
    uint2 o; o.x = pack2(v.x, v.y); o.y = pack2(v.z, v.w);
    *(uint2*)(g_wih2 + (size_t)(nt * 16 + s) * ASTRIP + nr * 40 + kc) = o;
}
__global__ void prep_whh_kernel(const float* __restrict__ W) {
    int i4 = blockIdx.x * 256 + threadIdx.x;
    if (i4 >= G4 * HID / 4) return;
    int r = i4 >> 8, kq = (i4 & 255) * 4;
    int g = r >> 10, j = r & 1023;
    int np = j * 4 + g;
    int nb = np >> 5, nr = np & 31;
    int s = kq >> 5, kc = kq & 31;
    float4 v = *(const float4*)(W + (size_t)r * HID + kq);
    uint2 o; o.x = pack2(v.x, v.y); o.y = pack2(v.z, v.w);
    *(uint2*)(g_whh2 + (size_t)(nb * 32 + s) * BSTRIP + nr * 40 + kc) = o;
}
__global__ void prep_bias_kernel(const float* __restrict__ bih, const float* __restrict__ bhh) {
    int r = blockIdx.x * 256 + threadIdx.x;
    if (r >= G4) return;
    int g = r >> 10, j = r & 1023;
    g_bias[j * 4 + g] = bih[r] + bhh[r];
}
__global__ void init_state_kernel(const float* __restrict__ h0, const float* __restrict__ c0) {
    int idx = blockIdx.x * 256 + threadIdx.x;
    if (idx == 0) g_cnt = 0u;
    if (idx >= BATCH * HID) return;
    g_c[idx] = c0[idx];
    int b = idx >> 10, j = idx & 1023;
    int s = j >> 5, kc = j & 31;
    g_haug2[0][(size_t)s * ASTRIP + b * 40 + kc] = __float2half(h0[idx]);
}

// ---------------- phase A: x_proj GEMM, persistent-B schedule ---------------
// Grid = 128 blocks = 32 nt x 4 mt-quarters. Each block holds its full B tile
// (16 strips = 160KB) in smem, then sweeps 128 mt-tiles streaming A strips
// linearly (strip G at base + G*ASTRIP) through a 4-deep 10KB ring.
// smem: B 163840 | A ring 4x10240 | bias 512 | mbars
#define XB_OFF    0
#define XA_OFF    163840
#define XBIAS_OFF 204800
#define XMBAR_OFF 205312
#define XPROJ_SMEM 205440

__global__ void __launch_bounds__(256) xproj_kernel() {
    extern __shared__ char dyn[];
    __half* smB = (__half*)(dyn + XB_OFF);     // [16 strips][5120]
    __half* smA = (__half*)(dyn + XA_OFF);     // ring [4][5120]
    float* sbias = (float*)(dyn + XBIAS_OFF);  // [128]
    uint64_t* mbar = (uint64_t*)(dyn + XMBAR_OFF); // 0-3 ring, 4 B

    const int tid = threadIdx.x, warp = tid >> 5, lane = tid & 31;
    const int nt = blockIdx.x >> 2, q = blockIdx.x & 3;
    const int nt0 = nt * 128;
    const __half* Ab = g_xaug2 + (size_t)(q * 128) * (16 * ASTRIP);
    const int wm = warp >> 1, wn = warp & 1;

    if (tid == 0) {
        for (int i = 0; i < 5; i++) mbar_init(&mbar[i], 1);
        asm volatile("fence.proxy.async.shared::cta;" ::: "memory");
        uint32_t mB = cvta_s(&mbar[4]);
        mbar_expect(mB, 163840);
        bulk_g2s(smB, g_wih2 + (size_t)nt * (16 * ASTRIP), 163840, mB);
    }
    __syncthreads();
    if (tid < 128) sbias[tid] = g_bias[nt0 + tid];

    auto issueA = [&](int G) {
        int buf = G & 3;
        uint32_t m = cvta_s(&mbar[buf]);
        mbar_expect(m, 10240);
        bulk_g2s(smA + buf * ASTRIP, Ab + (size_t)G * ASTRIP, 10240, m);
    };
    if (tid == 0) {
#pragma unroll
        for (int G = 0; G < 4; ++G) issueA(G);
    }
    mbar_wait(&mbar[4], 0);
    __syncthreads();     // bias + B visible to all

    for (int mt = 0; mt < 128; ++mt) {
        float c[2][8][4];
#pragma unroll
        for (int i = 0; i < 2; i++)
#pragma unroll
            for (int j = 0; j < 8; j++)
#pragma unroll
                for (int p = 0; p < 4; p++) c[i][j][p] = 0.f;

        for (int s = 0; s < 16; ++s) {
            int G = mt * 16 + s, buf = G & 3, par = (G >> 2) & 1;
            mbar_wait(&mbar[buf], par);
            const __half* A0 = smA + buf * ASTRIP;
            const __half* B0 = smB + (size_t)s * ASTRIP;
#pragma unroll
            for (int kk = 0; kk < 2; ++kk) {
                int k16 = kk * 16;
                uint32_t a[2][4];
#pragma unroll
                for (int im = 0; im < 2; ++im) {
                    int aoff = (wm * 32 + im * 16 + (lane & 15)) * 40 + k16 + ((lane >> 4) << 3);
                    ldsm4(a[im], cvta_s(A0 + aoff));
                }
                uint32_t b[4][4];
#pragma unroll
                for (int h = 0; h < 4; ++h) {
                    int boff = (wn * 64 + h * 16 + ((lane >> 4) << 3) + (lane & 7)) * 40
                               + k16 + (((lane >> 3) & 1) << 3);
                    ldsm4(b[h], cvta_s(B0 + boff));
                }
#pragma unroll
                for (int im = 0; im < 2; ++im)
#pragma unroll
                    for (int ntg = 0; ntg < 8; ++ntg)
                        mma_f16(c[im][ntg], a[im], b[ntg >> 1][(ntg & 1) * 2], b[ntg >> 1][(ntg & 1) * 2 + 1]);
            }
            __syncthreads();                 // all reads of buf done
            if (tid == 0 && G + 4 < 128 * 16) issueA(G + 4);
        }

        // epilogue for this mt: + bias, fp32 blocked store [t][nb][b][32]
        int mtg = q * 128 + mt;
        int gid = lane >> 2, tg = lane & 3;
#pragma unroll
        for (int im = 0; im < 2; ++im) {
            int rloc0 = wm * 32 + im * 16 + gid;
#pragma unroll
            for (int ntg = 0; ntg < 8; ++ntg) {
                int cloc = wn * 64 + ntg * 8 + tg * 2;
                int col = nt0 + cloc;
                float b0 = sbias[cloc], b1 = sbias[cloc + 1];
                int nbt = col >> 5, cc = col & 31;
#pragma unroll
                for (int rr = 0; rr < 2; ++rr) {
                    int mloc = rloc0 + rr * 8;
                    float* o = g_xproj +
                        ((((size_t)mtg * NBLK + nbt) * BATCH + mloc) * 32 + cc);
                    o[0] = c[im][ntg][rr * 2 + 0] + b0;
                    o[1] = c[im][ntg][rr * 2 + 1] + b1;
                }
            }
        }
    }
}

// ---------------- persistent LSTM kernel: all 512 steps ---------------------
// smem: W 81920 | A ring 4x20480 | XP 16384 | C 4096 | mbars
// Stage = 2 strips (20480B contiguous), 16 stages/step, ring depth 4.
#define SMW_OFF   0
#define SMA_OFF   81920
#define SMXP_OFF  (81920 + 81920)           // 163840
#define SMC_OFF   (SMXP_OFF + 16384)        // 180224
#define SMBAR_OFF (SMC_OFF + 4096)          // 184320
#define PERSIST_SMEM (SMBAR_OFF + 128)      // 184448

__global__ void __launch_bounds__(256) lstm_persist_kernel() {
    extern __shared__ char dyn[];
    __half* smW = (__half*)(dyn + SMW_OFF);     // [32][1280]
    __half* smA = (__half*)(dyn + SMA_OFF);     // ring [4][2*5120]
    float* smXP  = (float*)(dyn + SMXP_OFF);
    float* smC   = (float*)(dyn + SMC_OFF);
    float* gates = (float*)(dyn + SMA_OFF);     // alias over A ring (post-compute)
    uint64_t* mb = (uint64_t*)(dyn + SMBAR_OFF); // 0-3 A ring, 4 W, 5 XP

    const int tid = threadIdx.x, warp = tid >> 5, lane = tid & 31;
    const int nb = blockIdx.x, m0 = warp * 16;

    if (tid == 0) {
        for (int i = 0; i < 6; i++) mbar_init(&mb[i], 1);
        asm volatile("fence.proxy.async.shared::cta;" ::: "memory");
        uint32_t mW = cvta_s(&mb[4]);
        mbar_expect(mW, 81920);
        bulk_g2s(smW, g_whh2 + (size_t)nb * (32 * BSTRIP), 81920, mW);
    }
    __syncthreads();
    for (int i = tid; i < 1024; i += 256) {
        int b = i >> 3, jj = i & 7;
        smC[i] = g_c[b * HID + nb * 8 + jj];
    }
    mbar_wait(&mb[4], 0);

    for (int t = 0; t < S_LEN; ++t) {
        const __half* __restrict__ Ab = g_haug2[t & 1];
        __half* __restrict__ hdst = g_haug2[(t + 1) & 1];

        auto issueA = [&](int g) {                 // stage g = strips 2g,2g+1
            int buf = g & 3;
            uint32_t m = cvta_s(&mb[buf]);
            mbar_expect(m, 20480);
            bulk_g2s(smA + buf * (2 * ASTRIP), Ab + (size_t)(2 * g) * ASTRIP, 20480, m);
        };

        if (tid == 0) {
            if (t == 0) {
                uint32_t mXP = cvta_s(&mb[5]);
                mbar_expect(mXP, 16384);
                bulk_g2s(smXP, (const char*)g_xproj +
                         (((size_t)t * NBLK + nb) * BATCH * 32) * sizeof(float), 16384, mXP);
            }
#pragma unroll
            for (int g = 0; g < 4; ++g) issueA(g);
        }

        float c4[4][4];
#pragma unroll
        for (int i = 0; i < 4; i++)
#pragma unroll
            for (int j = 0; j < 4; j++) c4[i][j] = 0.f;

        for (int g = 0; g < 16; ++g) {
            int buf = g & 3;
            int par = (t * 4 + (g >> 2)) & 1;      // buffer use-count parity
            mbar_wait(&mb[buf], par);
#pragma unroll
            for (int ss = 0; ss < 2; ++ss) {
                int s = 2 * g + ss;
                const __half* A0 = smA + buf * (2 * ASTRIP) + ss * ASTRIP;
                const __half* B0 = smW + (size_t)s * BSTRIP;
#pragma unroll
                for (int kk = 0; kk < 2; ++kk) {
                    int k16 = kk * 16;
                    int aoff = (m0 + (lane & 15)) * 40 + k16 + ((lane >> 4) << 3);
                    uint32_t a[4];
                    ldsm4(a, cvta_s(A0 + aoff));
                    uint32_t b[2][4];
#pragma unroll
                    for (int h = 0; h < 2; ++h) {
                        int boff = (h * 16 + ((lane >> 4) << 3) + (lane & 7)) * 40
                                   + k16 + (((lane >> 3) & 1) << 3);
                        ldsm4(b[h], cvta_s(B0 + boff));
                    }
#pragma unroll
                    for (int nt = 0; nt < 4; ++nt)
                        mma_f16(c4[nt], a, b[nt >> 1][(nt & 1) * 2], b[nt >> 1][(nt & 1) * 2 + 1]);
                }
            }
            __syncthreads();                 // all reads of buf done
            if (tid == 0 && g + 4 < 16) issueA(g + 4);
        }

        // stash gate pre-activations (aliases A ring; all stages consumed)
        int gid = lane >> 2, tg = lane & 3;
#pragma unroll
        for (int nt = 0; nt < 4; ++nt) {
            int col = nt * 8 + tg * 2;
            gates[(m0 + gid) * 33 + col]         = c4[nt][0];
            gates[(m0 + gid) * 33 + col + 1]     = c4[nt][1];
            gates[(m0 + gid + 8) * 33 + col]     = c4[nt][2];
            gates[(m0 + gid + 8) * 33 + col + 1] = c4[nt][3];
        }
        __syncthreads();
        mbar_wait(&mb[5], t & 1);

        // fused LSTM cell update: 512 pairs (b, jj0..jj0+1), 2 per thread
        // activations via HW tanh: 5 MUFU per (b,jj) instead of 10 MUFU+RCP
#pragma unroll
        for (int i = 0; i < 2; ++i) {
            int q = tid + i * 256;          // 0..511
            int b = q >> 2, jj0 = (q & 3) * 2;
            float4 xv0 = *(const float4*)(smXP + b * 32 + jj0 * 4);
            float4 xv1 = *(const float4*)(smXP + b * 32 + jj0 * 4 + 4);
            const float* gb = gates + b * 33;
            float i0 = gb[jj0 * 4 + 0] + xv0.x, f0 = gb[jj0 * 4 + 1] + xv0.y;
            float g0 = gb[jj0 * 4 + 2] + xv0.z, o0 = gb[jj0 * 4 + 3] + xv0.w;
            float i1 = gb[jj0 * 4 + 4] + xv1.x, f1 = gb[jj0 * 4 + 5] + xv1.y;
            float g1 = gb[jj0 * 4 + 6] + xv1.z, o1 = gb[jj0 * 4 + 7] + xv1.w;
            float cn0 = fsigmoid(f0) * smC[b * 8 + jj0]     + fsigmoid(i0) * ftanh(g0);
            float cn1 = fsigmoid(f1) * smC[b * 8 + jj0 + 1] + fsigmoid(i1) * ftanh(g1);
            float hn0 = fsigmoid(o0) * ftanh(cn0);
            float hn1 = fsigmoid(o1) * ftanh(cn1);
            smC[b * 8 + jj0]     = cn0;
            smC[b * 8 + jj0 + 1] = cn1;
            int j0 = nb * 8 + jj0;
            if (t == S_LEN - 1) {
                g_h[b * HID + j0]     = hn0;
                g_h[b * HID + j0 + 1] = hn1;
            }
            int sA = j0 >> 5, kc = j0 & 31;
            __half2 hv = __floats2half2_rn(hn0, hn1);
            *(__half2*)(hdst + (size_t)sA * ASTRIP + b * 40 + kc) = hv;
        }

        if (t + 1 < S_LEN) {
            // grid barrier: arrive, prefetch next XP during the spin, wait
            __threadfence();
            __syncthreads();
            if (tid == 0) {
                unsigned target = (unsigned)(t + 1) * NBLK;
                atomicAdd(&g_cnt, 1u);
                uint32_t mXP = cvta_s(&mb[5]);
                mbar_expect(mXP, 16384);
                bulk_g2s(smXP, (const char*)g_xproj +
                         (((size_t)(t + 1) * NBLK + nb) * BATCH * 32) * sizeof(float),
                         16384, mXP);
                while (*((volatile unsigned*)&g_cnt) < target) __nanosleep(16);
            }
            __syncthreads();
            __threadfence();
        }
    }
}

// ---------------- decoder + softmax over batch dim -------------------------
__global__ void decoder_kernel(const float* __restrict__ Wdec,
                               const float* __restrict__ bdec,
                               float* __restrict__ out) {
    __shared__ float sl[512];
    __shared__ float red[8];
    int tid = threadIdx.x;
    int b = tid >> 2, o = tid & 3;
    const float4* h4 = (const float4*)(g_h + b * HID);
    const float4* w4 = (const float4*)(Wdec + o * HID);
    float acc = bdec[o];
    for (int k = 0; k < HID / 4; ++k) {
        float4 hv = h4[k], wv = w4[k];
        acc += hv.x * wv.x + hv.y * wv.y + hv.z * wv.z + hv.w * wv.w;
    }
    sl[tid] = acc;
    __syncthreads();
    if (tid < 4) {
        float mx = -1e30f;
        for (int bb = 0; bb < 128; ++bb) mx = fmaxf(mx, sl[bb * 4 + tid]);
        float s = 0.f;
        for (int bb = 0; bb < 128; ++bb) s += expf(sl[bb * 4 + tid] - mx);
        red[tid] = mx; red[4 + tid] = s;
    }
    __syncthreads();
    out[tid] = expf(sl[tid] - red[o]) / red[4 + o];
}

// ---------------- launch ----------------
extern "C" void kernel_launch(void* const* d_in, const int* in_sizes, int n_in,
                              void* d_out, int out_size) {
    const float* inputs = (const float*)d_in[0];
    const float* h0     = (const float*)d_in[1];
    const float* c0     = (const float*)d_in[2];
    const float* Wih    = (const float*)d_in[3];
    const float* Whh    = (const float*)d_in[4];
    const float* bih    = (const float*)d_in[5];
    const float* bhh    = (const float*)d_in[6];
    const float* Wdec   = (const float*)d_in[7];
    const float* bdec   = (const float*)d_in[8];
    float* out = (float*)d_out;

    cudaFuncSetAttribute(xproj_kernel, cudaFuncAttributeMaxDynamicSharedMemorySize, XPROJ_SMEM);
    cudaFuncSetAttribute(lstm_persist_kernel, cudaFuncAttributeMaxDynamicSharedMemorySize, PERSIST_SMEM);

    prep_wih_kernel<<<(G4 * INPUT / 4 + 255) / 256, 256>>>(Wih);
    prep_whh_kernel<<<(G4 * HID / 4 + 255) / 256, 256>>>(Whh);
    prep_bias_kernel<<<(G4 + 255) / 256, 256>>>(bih, bhh);
    prep_x_kernel<<<(int)(((size_t)MX * INPUT / 4 + 255) / 256), 256>>>(inputs);
    init_state_kernel<<<(BATCH * HID + 255) / 256, 256>>>(h0, c0);

    xproj_kernel<<<128, 256, XPROJ_SMEM>>>();

    lstm_persist_kernel<<<NBLK, 256, PERSIST_SMEM>>>();

    decoder_kernel<<<1, 512>>>(Wdec, bdec, out);
}

// round 15
// speedup vs baseline: 1.1221x; 1.1221x over previous
#include <cuda_runtime.h>
#include <cuda_fp16.h>
#include <math.h>
#include <stdint.h>

#define S_LEN 512
#define BATCH 128
#define INPUT 512
#define HID   1024
#define G4    4096            // 4*HID, permuted rows: n' = j*4 + gate
#define MX    (S_LEN*BATCH)   // 65536
#define NBLK  128

// K-strips of 32 fp16, padded pitch 40 (80B rows, conflict-free ldmatrix).
// A-strip = 128 rows x 40 = 5120 elems (10240B). B-strip = 32 x 40 (2560B).
#define ASTRIP 5120
#define BSTRIP 1280

// ---------------- device scratch (static, no runtime allocation) ----------
// x image: [mt 512][s 16][128][40] fp16
__device__ __half g_xaug2[(size_t)512 * 16 * ASTRIP];     // ~84MB
// W_ih image: [nt 32][s 16][128][40] fp16
__device__ __half g_wih2[(size_t)32 * 16 * ASTRIP];       // ~5.2MB
// W_hh image: [nb 128][s 32][32][40] fp16
__device__ __half g_whh2[(size_t)128 * 32 * BSTRIP];      // ~10.5MB
__device__ float  g_bias[G4];
// x_proj blocked for step prefetch: [t 512][nb 128][b 128][32] fp16 (0.5GiB)
__device__ __half g_xproj[(size_t)S_LEN * NBLK * BATCH * 32];
__device__ float  g_c[BATCH * HID];
__device__ float  g_h[BATCH * HID];
// recurrent h: [pp 2][s 32][128 b][40] fp16, ping-pong
__device__ __half g_haug2[2][32 * ASTRIP];
// grid barrier: monotonic counter, reset by init_state_kernel each launch
__device__ unsigned g_cnt;

// ---------------- helpers ----------------
__device__ __forceinline__ uint32_t cvta_s(const void* p) {
    return (uint32_t)__cvta_generic_to_shared(p);
}
__device__ __forceinline__ void ldsm4(uint32_t r[4], uint32_t a) {
    asm volatile("ldmatrix.sync.aligned.m8n8.x4.shared.b16 {%0,%1,%2,%3}, [%4];\n"
                 : "=r"(r[0]), "=r"(r[1]), "=r"(r[2]), "=r"(r[3]) : "r"(a));
}
__device__ __forceinline__ void mma_f16(float* c, const uint32_t* a,
                                        uint32_t b0, uint32_t b1) {
    asm volatile(
        "mma.sync.aligned.m16n8k16.row.col.f32.f16.f16.f32 "
        "{%0,%1,%2,%3},{%4,%5,%6,%7},{%8,%9},{%0,%1,%2,%3};\n"
        : "+f"(c[0]), "+f"(c[1]), "+f"(c[2]), "+f"(c[3])
        : "r"(a[0]), "r"(a[1]), "r"(a[2]), "r"(a[3]), "r"(b0), "r"(b1));
}
__device__ __forceinline__ void mbar_init(void* m, uint32_t cnt) {
    asm volatile("mbarrier.init.shared.b64 [%0], %1;\n"
                 :: "r"(cvta_s(m)), "r"(cnt) : "memory");
}
__device__ __forceinline__ void mbar_expect(uint32_t mb, uint32_t bytes) {
    asm volatile("mbarrier.arrive.expect_tx.shared.b64 _, [%0], %1;\n"
                 :: "r"(mb), "r"(bytes) : "memory");
}
__device__ __forceinline__ void bulk_g2s(void* dst, const void* src,
                                         uint32_t bytes, uint32_t mb) {
    asm volatile("cp.async.bulk.shared::cta.global.mbarrier::complete_tx::bytes "
                 "[%0], [%1], %2, [%3];\n"
                 :: "r"(cvta_s(dst)), "l"(src), "r"(bytes), "r"(mb) : "memory");
}
__device__ __forceinline__ void mbar_wait(void* m, uint32_t parity) {
    uint32_t a = cvta_s(m);
    asm volatile(
        "{\n.reg .pred P;\n"
        "W_%=:\n"
        "mbarrier.try_wait.parity.shared.b64 P, [%0], %1;\n"
        "@!P bra W_%=;\n}\n"
        :: "r"(a), "r"(parity) : "memory");
}
// HW tanh (1 MUFU op, sm_75+). sigmoid via tanh: 1 MUFU + FMA, no RCP.
__device__ __forceinline__ float tanh_hw(float x) {
    float y;
    asm("tanh.approx.f32 %0, %1;" : "=f"(y) : "f"(x));
    return y;
}
__device__ __forceinline__ float fsigmoid(float x) {
    return fmaf(tanh_hw(0.5f * x), 0.5f, 0.5f);
}
__device__ __forceinline__ float ftanh(float x) { return tanh_hw(x); }
__device__ __forceinline__ uint32_t pack2(float a, float b) {
    __half2 h = __floats2half2_rn(a, b);
    return *(uint32_t*)&h;
}

// ---------------- prep kernels (vectorized) ----------------
__global__ void prep_x_kernel(const float* __restrict__ X) {
    size_t i4 = (size_t)blockIdx.x * 256 + threadIdx.x;
    if (i4 >= (size_t)MX * INPUT / 4) return;
    int m = (int)(i4 >> 7), kq = (int)(i4 & 127) * 4;
    int mt = m >> 7, mr = m & 127;
    int s = kq >> 5, kc = kq & 31;
    float4 v = *(const float4*)(X + (size_t)m * INPUT + kq);
    uint2 o; o.x = pack2(v.x, v.y); o.y = pack2(v.z, v.w);
    *(uint2*)(g_xaug2 + (size_t)(mt * 16 + s) * ASTRIP + mr * 40 + kc) = o;
}
__global__ void prep_wih_kernel(const float* __restrict__ W) {
    int i4 = blockIdx.x * 256 + threadIdx.x;
    if (i4 >= G4 * INPUT / 4) return;
    int r = i4 >> 7, kq = (i4 & 127) * 4;
    int g = r >> 10, j = r & 1023;
    int np = j * 4 + g;
    int nt = np >> 7, nr = np & 127;
    int s = kq >> 5, kc = kq & 31;
    float4 v = *(const float4*)(W + (size_t)r * INPUT + kq);
    uint2 o; o.x = pack2(v.x, v.y); o.y = pack2(v.z, v.w);
    *(uint2*)(g_wih2 + (size_t)(nt * 16 + s) * ASTRIP + nr * 40 + kc) = o;
}
__global__ void prep_whh_kernel(const float* __restrict__ W) {
    int i4 = blockIdx.x * 256 + threadIdx.x;
    if (i4 >= G4 * HID / 4) return;
    int r = i4 >> 8, kq = (i4 & 255) * 4;
    int g = r >> 10, j = r & 1023;
    int np = j * 4 + g;
    int nb = np >> 5, nr = np & 31;
    int s = kq >> 5, kc = kq & 31;
    float4 v = *(const float4*)(W + (size_t)r * HID + kq);
    uint2 o; o.x = pack2(v.x, v.y); o.y = pack2(v.z, v.w);
    *(uint2*)(g_whh2 + (size_t)(nb * 32 + s) * BSTRIP + nr * 40 + kc) = o;
}
__global__ void prep_bias_kernel(const float* __restrict__ bih, const float* __restrict__ bhh) {
    int r = blockIdx.x * 256 + threadIdx.x;
    if (r >= G4) return;
    int g = r >> 10, j = r & 1023;
    g_bias[j * 4 + g] = bih[r] + bhh[r];
}
__global__ void init_state_kernel(const float* __restrict__ h0, const float* __restrict__ c0) {
    int idx = blockIdx.x * 256 + threadIdx.x;
    if (idx == 0) g_cnt = 0u;
    if (idx >= BATCH * HID) return;
    g_c[idx] = c0[idx];
    int b = idx >> 10, j = idx & 1023;
    int s = j >> 5, kc = j & 31;
    g_haug2[0][(size_t)s * ASTRIP + b * 40 + kc] = __float2half(h0[idx]);
}

// ---------------- phase A: x_proj GEMM (M=65536, N=4096, K=512, fp16) ------
__global__ void __launch_bounds__(256) xproj_kernel() {
    __shared__ __half As[2][ASTRIP];
    __shared__ __half Bs[2][ASTRIP];
    __shared__ uint64_t mbar[2];

    const int tid = threadIdx.x, warp = tid >> 5, lane = tid & 31;
    const int nt0 = blockIdx.x * 128, mt0 = blockIdx.y * 128;
    const __half* Ab = g_xaug2 + (size_t)blockIdx.y * (16 * ASTRIP);
    const __half* Bb = g_wih2 + (size_t)blockIdx.x * (16 * ASTRIP);
    const int wm = warp >> 1, wn = warp & 1;

    if (tid == 0) {
        mbar_init(&mbar[0], 1); mbar_init(&mbar[1], 1);
        asm volatile("fence.proxy.async.shared::cta;" ::: "memory");
    }
    __syncthreads();

    float c[2][8][4];
#pragma unroll
    for (int i = 0; i < 2; i++)
#pragma unroll
        for (int j = 0; j < 8; j++)
#pragma unroll
            for (int q = 0; q < 4; q++) c[i][j][q] = 0.f;

    auto issue = [&](int s, int buf) {
        uint32_t mb = cvta_s(&mbar[buf]);
        mbar_expect(mb, 20480);
        bulk_g2s(As[buf], Ab + (size_t)s * ASTRIP, 10240, mb);
        bulk_g2s(Bs[buf], Bb + (size_t)s * ASTRIP, 10240, mb);
    };

    if (tid == 0) { issue(0, 0); issue(1, 1); }
    for (int s = 0; s < 16; ++s) {
        int buf = s & 1, par = (s >> 1) & 1;
        mbar_wait(&mbar[buf], par);
#pragma unroll
        for (int kk = 0; kk < 2; ++kk) {
            int k16 = kk * 16;
            uint32_t a[2][4];
#pragma unroll
            for (int im = 0; im < 2; ++im) {
                int aoff = (wm * 32 + im * 16 + (lane & 15)) * 40 + k16 + ((lane >> 4) << 3);
                ldsm4(a[im], cvta_s(&As[buf][aoff]));
            }
            uint32_t b[4][4];
#pragma unroll
            for (int h = 0; h < 4; ++h) {
                int boff = (wn * 64 + h * 16 + ((lane >> 4) << 3) + (lane & 7)) * 40
                           + k16 + (((lane >> 3) & 1) << 3);
                ldsm4(b[h], cvta_s(&Bs[buf][boff]));
            }
#pragma unroll
            for (int im = 0; im < 2; ++im)
#pragma unroll
                for (int nt = 0; nt < 8; ++nt)
                    mma_f16(c[im][nt], a[im], b[nt >> 1][(nt & 1) * 2], b[nt >> 1][(nt & 1) * 2 + 1]);
        }
        __syncthreads();
        if (tid == 0 && s + 2 < 16) issue(s + 2, buf);
    }
    // epilogue: + bias, fp16 blocked store [t][nb][b][32]
    int gid = lane >> 2, tg = lane & 3;
#pragma unroll
    for (int im = 0; im < 2; ++im) {
        int rb0 = mt0 + wm * 32 + im * 16 + gid;
#pragma unroll
        for (int nt = 0; nt < 8; ++nt) {
            int col = nt0 + wn * 64 + nt * 8 + tg * 2;
            float b0 = __ldg(&g_bias[col]), b1 = __ldg(&g_bias[col + 1]);
            int nbt = col >> 5, cc = col & 31;
#pragma unroll
            for (int rr = 0; rr < 2; ++rr) {
                int m = rb0 + rr * 8;
                __half2* o = (__half2*)(g_xproj +
                    ((((size_t)(m >> 7) * NBLK + nbt) * BATCH + (m & 127)) * 32 + cc));
                *o = __floats2half2_rn(c[im][nt][rr * 2 + 0] + b0,
                                       c[im][nt][rr * 2 + 1] + b1);
            }
        }
    }
}

// ---------------- persistent LSTM kernel: all 512 steps ---------------------
// smem: W 81920 | A ring 3x40960 | XP 8192 | C 4096 | mbars
// Stage = 4 strips (40960B contiguous), 8 stages/step, ring depth 3.
#define SMW_OFF   0
#define SMA_OFF   81920
#define SMXP_OFF  (81920 + 122880)          // 204800
#define SMC_OFF   (SMXP_OFF + 8192)         // 212992
#define SMBAR_OFF (SMC_OFF + 4096)          // 217088
#define PERSIST_SMEM (SMBAR_OFF + 128)      // 217216

__global__ void __launch_bounds__(256) lstm_persist_kernel() {
    extern __shared__ char dyn[];
    __half* smW = (__half*)(dyn + SMW_OFF);     // [32][1280]
    __half* smA = (__half*)(dyn + SMA_OFF);     // ring [3][4*5120]
    __half* smXP = (__half*)(dyn + SMXP_OFF);   // [128][32] fp16
    float* smC   = (float*)(dyn + SMC_OFF);
    float* gates = (float*)(dyn + SMA_OFF);     // alias over A ring (post-compute)
    uint64_t* mb = (uint64_t*)(dyn + SMBAR_OFF); // 0-2 A ring, 3 W, 4 XP

    const int tid = threadIdx.x, warp = tid >> 5, lane = tid & 31;
    const int nb = blockIdx.x, m0 = warp * 16;

    if (tid == 0) {
        for (int i = 0; i < 5; i++) mbar_init(&mb[i], 1);
        asm volatile("fence.proxy.async.shared::cta;" ::: "memory");
        uint32_t mW = cvta_s(&mb[3]);
        mbar_expect(mW, 81920);
        bulk_g2s(smW, g_whh2 + (size_t)nb * (32 * BSTRIP), 81920, mW);
    }
    __syncthreads();
    for (int i = tid; i < 1024; i += 256) {
        int b = i >> 3, jj = i & 7;
        smC[i] = g_c[b * HID + nb * 8 + jj];
    }
    mbar_wait(&mb[3], 0);

    // per-buffer phase bits, tracked identically by all threads
    unsigned ph0 = 0, ph1 = 0, ph2 = 0;

    for (int t = 0; t < S_LEN; ++t) {
        const __half* __restrict__ Ab = g_haug2[t & 1];
        __half* __restrict__ hdst = g_haug2[(t + 1) & 1];

        auto issueA = [&](int g) {                 // stage g = strips 4g..4g+3
            int buf = g % 3;
            uint32_t m = cvta_s(&mb[buf]);
            mbar_expect(m, 40960);
            bulk_g2s(smA + buf * (4 * ASTRIP), Ab + (size_t)(4 * g) * ASTRIP, 40960, m);
        };

        if (tid == 0) {
            if (t == 0) {
                uint32_t mXP = cvta_s(&mb[4]);
                mbar_expect(mXP, 8192);
                bulk_g2s(smXP, (const char*)g_xproj +
                         (((size_t)t * NBLK + nb) * BATCH * 32) * sizeof(__half), 8192, mXP);
            }
            issueA(0); issueA(1); issueA(2);
        }

        float c4[4][4];
#pragma unroll
        for (int i = 0; i < 4; i++)
#pragma unroll
            for (int j = 0; j < 4; j++) c4[i][j] = 0.f;

        for (int g = 0; g < 8; ++g) {
            int buf = g % 3;
            unsigned par = (buf == 0) ? ph0 : (buf == 1) ? ph1 : ph2;
            mbar_wait(&mb[buf], par);
            if (buf == 0) ph0 ^= 1; else if (buf == 1) ph1 ^= 1; else ph2 ^= 1;
#pragma unroll
            for (int ss = 0; ss < 4; ++ss) {
                int s = 4 * g + ss;
                const __half* A0 = smA + buf * (4 * ASTRIP) + ss * ASTRIP;
                const __half* B0 = smW + (size_t)s * BSTRIP;
#pragma unroll
                for (int kk = 0; kk < 2; ++kk) {
                    int k16 = kk * 16;
                    int aoff = (m0 + (lane & 15)) * 40 + k16 + ((lane >> 4) << 3);
                    uint32_t a[4];
                    ldsm4(a, cvta_s(A0 + aoff));
                    uint32_t b[2][4];
#pragma unroll
                    for (int h = 0; h < 2; ++h) {
                        int boff = (h * 16 + ((lane >> 4) << 3) + (lane & 7)) * 40
                                   + k16 + (((lane >> 3) & 1) << 3);
                        ldsm4(b[h], cvta_s(B0 + boff));
                    }
#pragma unroll
                    for (int nt = 0; nt < 4; ++nt)
                        mma_f16(c4[nt], a, b[nt >> 1][(nt & 1) * 2], b[nt >> 1][(nt & 1) * 2 + 1]);
                }
            }
            __syncthreads();                 // all reads of buf done
            if (tid == 0 && g + 3 < 8) issueA(g + 3);
        }

        // stash gate pre-activations (aliases A ring; all stages consumed)
        int gid = lane >> 2, tg = lane & 3;
#pragma unroll
        for (int nt = 0; nt < 4; ++nt) {
            int col = nt * 8 + tg * 2;
            gates[(m0 + gid) * 33 + col]         = c4[nt][0];
            gates[(m0 + gid) * 33 + col + 1]     = c4[nt][1];
            gates[(m0 + gid + 8) * 33 + col]     = c4[nt][2];
            gates[(m0 + gid + 8) * 33 + col + 1] = c4[nt][3];
        }
        __syncthreads();
        mbar_wait(&mb[4], t & 1);

        // fused LSTM cell update: 512 pairs (b, jj0..jj0+1), 2 per thread
        // activations via HW tanh: 5 MUFU per (b,jj)
#pragma unroll
        for (int i = 0; i < 2; ++i) {
            int q = tid + i * 256;          // 0..511
            int b = q >> 2, jj0 = (q & 3) * 2;
            const __half* xp = smXP + b * 32 + jj0 * 4;
            float2 p0 = __half22float2(*(const __half2*)(xp + 0));
            float2 p1 = __half22float2(*(const __half2*)(xp + 2));
            float2 p2 = __half22float2(*(const __half2*)(xp + 4));
            float2 p3 = __half22float2(*(const __half2*)(xp + 6));
            const float* gb = gates + b * 33;
            float i0 = gb[jj0 * 4 + 0] + p0.x, f0 = gb[jj0 * 4 + 1] + p0.y;
            float g0 = gb[jj0 * 4 + 2] + p1.x, o0 = gb[jj0 * 4 + 3] + p1.y;
            float i1 = gb[jj0 * 4 + 4] + p2.x, f1 = gb[jj0 * 4 + 5] + p2.y;
            float g1 = gb[jj0 * 4 + 6] + p3.x, o1 = gb[jj0 * 4 + 7] + p3.y;
            float cn0 = fsigmoid(f0) * smC[b * 8 + jj0]     + fsigmoid(i0) * ftanh(g0);
            float cn1 = fsigmoid(f1) * smC[b * 8 + jj0 + 1] + fsigmoid(i1) * ftanh(g1);
            float hn0 = fsigmoid(o0) * ftanh(cn0);
            float hn1 = fsigmoid(o1) * ftanh(cn1);
            smC[b * 8 + jj0]     = cn0;
            smC[b * 8 + jj0 + 1] = cn1;
            int j0 = nb * 8 + jj0;
            if (t == S_LEN - 1) {
                g_h[b * HID + j0]     = hn0;
                g_h[b * HID + j0 + 1] = hn1;
            }
            int sA = j0 >> 5, kc = j0 & 31;
            __half2 hv = __floats2half2_rn(hn0, hn1);
            *(__half2*)(hdst + (size_t)sA * ASTRIP + b * 40 + kc) = hv;
        }

        if (t + 1 < S_LEN) {
            // grid barrier: arrive, prefetch next XP during the spin, wait
            __threadfence();
            __syncthreads();
            if (tid == 0) {
                unsigned target = (unsigned)(t + 1) * NBLK;
                atomicAdd(&g_cnt, 1u);
                uint32_t mXP = cvta_s(&mb[4]);
                mbar_expect(mXP, 8192);
                bulk_g2s(smXP, (const char*)g_xproj +
                         (((size_t)(t + 1) * NBLK + nb) * BATCH * 32) * sizeof(__half),
                         8192, mXP);
                while (*((volatile unsigned*)&g_cnt) < target) __nanosleep(16);
            }
            __syncthreads();
            __threadfence();
        }
    }
}

// ---------------- decoder + softmax over batch dim -------------------------
__global__ void decoder_kernel(const float* __restrict__ Wdec,
                               const float* __restrict__ bdec,
                               float* __restrict__ out) {
    __shared__ float sl[512];
    __shared__ float red[8];
    int tid = threadIdx.x;
    int b = tid >> 2, o = tid & 3;
    const float4* h4 = (const float4*)(g_h + b * HID);
    const float4* w4 = (const float4*)(Wdec + o * HID);
    float acc = bdec[o];
    for (int k = 0; k < HID / 4; ++k) {
        float4 hv = h4[k], wv = w4[k];
        acc += hv.x * wv.x + hv.y * wv.y + hv.z * wv.z + hv.w * wv.w;
    }
    sl[tid] = acc;
    __syncthreads();
    if (tid < 4) {
        float mx = -1e30f;
        for (int bb = 0; bb < 128; ++bb) mx = fmaxf(mx, sl[bb * 4 + tid]);
        float s = 0.f;
        for (int bb = 0; bb < 128; ++bb) s += expf(sl[bb * 4 + tid] - mx);
        red[tid] = mx; red[4 + tid] = s;
    }
    __syncthreads();
    out[tid] = expf(sl[tid] - red[o]) / red[4 + o];
}

// ---------------- launch ----------------
extern "C" void kernel_launch(void* const* d_in, const int* in_sizes, int n_in,
                              void* d_out, int out_size) {
    const float* inputs = (const float*)d_in[0];
    const float* h0     = (const float*)d_in[1];
    const float* c0     = (const float*)d_in[2];
    const float* Wih    = (const float*)d_in[3];
    const float* Whh    = (const float*)d_in[4];
    const float* bih    = (const float*)d_in[5];
    const float* bhh    = (const float*)d_in[6];
    const float* Wdec   = (const float*)d_in[7];
    const float* bdec   = (const float*)d_in[8];
    float* out = (float*)d_out;

    cudaFuncSetAttribute(lstm_persist_kernel, cudaFuncAttributeMaxDynamicSharedMemorySize, PERSIST_SMEM);

    prep_wih_kernel<<<(G4 * INPUT / 4 + 255) / 256, 256>>>(Wih);
    prep_whh_kernel<<<(G4 * HID / 4 + 255) / 256, 256>>>(Whh);
    prep_bias_kernel<<<(G4 + 255) / 256, 256>>>(bih, bhh);
    prep_x_kernel<<<(int)(((size_t)MX * INPUT / 4 + 255) / 256), 256>>>(inputs);
    init_state_kernel<<<(BATCH * HID + 255) / 256, 256>>>(h0, c0);

    xproj_kernel<<<dim3(32, 512), 256>>>();

    lstm_persist_kernel<<<NBLK, 256, PERSIST_SMEM>>>();

    decoder_kernel<<<1, 512>>>(Wdec, bdec, out);
}